// round 9
// baseline (speedup 1.0000x reference)
#include <cuda_runtime.h>
#include <cuda_fp16.h>
#include <cuda_bf16.h>

#define N_NODES 100000
#define N_EDGES 1600000
#define D_FEAT  64
#define UNITS   64
#define SCAN_B  1024
#define N_SCANB ((N_NODES + SCAN_B - 1) / SCAN_B)   // 98

// ---- scratch (__device__ globals; no allocations allowed) -----------------
__device__ int    g_deg[N_NODES];
__device__ int    g_excl[N_NODES];
__device__ int    g_off[N_NODES + 1];
__device__ int    g_bsum[128];
__device__ float  g_inv[N_NODES];
__device__ int    g_pos[N_EDGES];            // edge's rank within its target
__device__ int    g_sorted_src[N_EDGES];
__device__ uint4  g_xh4[N_NODES * 8];        // fp16 x_norm: 128 B per node row

// ---------------------------------------------------------------------------
__global__ void k_zero_deg() {
    int i = blockIdx.x * blockDim.x + threadIdx.x;
    if (i < N_NODES) g_deg[i] = 0;
}

// degree + per-edge rank in one atomic pass
__global__ void k_degree(const int* __restrict__ target) {
    int e = blockIdx.x * blockDim.x + threadIdx.x;
    if (e < N_EDGES) g_pos[e] = atomicAdd(&g_deg[target[e]], 1);
}

// ---- block-local exclusive scan of degrees --------------------------------
__global__ __launch_bounds__(SCAN_B) void k_scan1() {
    __shared__ int sh[SCAN_B];
    int tid = threadIdx.x;
    int i = blockIdx.x * SCAN_B + tid;
    int v = (i < N_NODES) ? g_deg[i] : 0;
    sh[tid] = v;
    __syncthreads();
    #pragma unroll
    for (int ofs = 1; ofs < SCAN_B; ofs <<= 1) {
        int t = (tid >= ofs) ? sh[tid - ofs] : 0;
        __syncthreads();
        sh[tid] += t;
        __syncthreads();
    }
    if (i < N_NODES) g_excl[i] = sh[tid] - v;
    if (tid == SCAN_B - 1) g_bsum[blockIdx.x] = sh[tid];
}

// ---- finish scan (per-block prefix of g_bsum) + inv + fp16 normalize ------
__global__ __launch_bounds__(SCAN_B) void k_scan3_norm(const float2* __restrict__ x2) {
    __shared__ float s_inv[SCAN_B];
    __shared__ int   s_add;

    int tid = threadIdx.x;
    int blk = blockIdx.x;

    // warp 0: sum of g_bsum[0..blk-1]
    if (tid < 32) {
        int acc = 0;
        for (int k = tid; k < blk; k += 32) acc += g_bsum[k];
        #pragma unroll
        for (int ofs = 16; ofs > 0; ofs >>= 1)
            acc += __shfl_down_sync(0xffffffff, acc, ofs);
        if (tid == 0) s_add = acc;
    }
    __syncthreads();
    int add = s_add;

    int i = blk * SCAN_B + tid;
    float inv = 0.f;
    if (i < N_NODES) {
        g_off[i] = g_excl[i] + add;
        inv = rsqrtf((float)g_deg[i]);
        g_inv[i] = inv;
    }
    s_inv[tid] = inv;
    if (i == 0) g_off[N_NODES] = N_EDGES;
    __syncthreads();

    // normalize this block's 1024 nodes: 1024*32 half2 elements, coalesced
    int base_node = blk * SCAN_B;
    __half2* xh2 = (__half2*)g_xh4;
    #pragma unroll
    for (int k = 0; k < 32; k++) {
        int j = k * SCAN_B + tid;           // 0 .. 32767
        int ln = j >> 5;                    // local node
        int node = base_node + ln;
        if (node < N_NODES) {
            float s = s_inv[ln];
            float2 v = x2[node * 32 + (j & 31)];
            v.x *= s; v.y *= s;
            xh2[node * 32 + (j & 31)] = __float22half2_rn(v);
        }
    }
}

// ---- place edges into CSR (no atomics) ------------------------------------
__global__ void k_place(const int* __restrict__ source,
                        const int* __restrict__ target) {
    int e = blockIdx.x * blockDim.x + threadIdx.x;
    if (e >= N_EDGES) return;
    g_sorted_src[g_off[target[e]] + g_pos[e]] = source[e];
}

// ---------------------------------------------------------------------------
// Fused gather + GEMV. Warp per node; 4 quarter-warps each own every 4th
// edge; per edge one LDG.128 of the 128-B fp16 row per lane-octet.
// ---------------------------------------------------------------------------
#define NODES_PER_WARP 2
#define FUSE_THREADS   1024
#define NODES_PER_BLK  (32 * NODES_PER_WARP)   // 64

__global__ __launch_bounds__(FUSE_THREADS) void k_fused(
    const float*  __restrict__ W,
    const float*  __restrict__ b,
    float* __restrict__ out)
{
    __shared__ float sW[D_FEAT * UNITS];     // 16 KB
    __shared__ float sB[UNITS];
    __shared__ float sP[32][D_FEAT];         // 8 KB

    int tid  = threadIdx.x;
    int lane = tid & 31;
    int w    = tid >> 5;
    int q    = lane >> 3;    // quarter-warp: which edge of a group of 4
    int fl   = lane & 7;     // uint4 slot within the 128-B row

    #pragma unroll
    for (int i = 0; i < (D_FEAT * UNITS) / FUSE_THREADS; i++)
        sW[tid + i * FUSE_THREADS] = W[tid + i * FUSE_THREADS];
    if (tid < UNITS) sB[tid] = b[tid];
    __syncthreads();

    #pragma unroll
    for (int r = 0; r < NODES_PER_WARP; r++) {
        int n = blockIdx.x * NODES_PER_BLK + w * NODES_PER_WARP + r;
        if (n >= N_NODES) return;

        int beg = g_off[n];
        int end = g_off[n + 1];
        float inv_t = g_inv[n];

        float2 a0 = make_float2(0.f, 0.f), a1 = a0, a2 = a0, a3 = a0;
        float2 b0 = a0, b1 = a0, b2 = a0, b3 = a0;

        int e = beg + q;
        for (; e + 4 < end; e += 8) {
            int s0 = g_sorted_src[e];
            int s1 = g_sorted_src[e + 4];
            uint4 u0 = g_xh4[s0 * 8 + fl];
            uint4 u1 = g_xh4[s1 * 8 + fl];
            const __half2* h0 = (const __half2*)&u0;
            const __half2* h1 = (const __half2*)&u1;
            float2 f;
            f = __half22float2(h0[0]); a0.x += f.x; a0.y += f.y;
            f = __half22float2(h0[1]); a1.x += f.x; a1.y += f.y;
            f = __half22float2(h0[2]); a2.x += f.x; a2.y += f.y;
            f = __half22float2(h0[3]); a3.x += f.x; a3.y += f.y;
            f = __half22float2(h1[0]); b0.x += f.x; b0.y += f.y;
            f = __half22float2(h1[1]); b1.x += f.x; b1.y += f.y;
            f = __half22float2(h1[2]); b2.x += f.x; b2.y += f.y;
            f = __half22float2(h1[3]); b3.x += f.x; b3.y += f.y;
        }
        if (e < end) {
            int s0 = g_sorted_src[e];
            uint4 u0 = g_xh4[s0 * 8 + fl];
            const __half2* h0 = (const __half2*)&u0;
            float2 f;
            f = __half22float2(h0[0]); a0.x += f.x; a0.y += f.y;
            f = __half22float2(h0[1]); a1.x += f.x; a1.y += f.y;
            f = __half22float2(h0[2]); a2.x += f.x; a2.y += f.y;
            f = __half22float2(h0[3]); a3.x += f.x; a3.y += f.y;
        }

        a0.x += b0.x; a0.y += b0.y;  a1.x += b1.x; a1.y += b1.y;
        a2.x += b2.x; a2.y += b2.y;  a3.x += b3.x; a3.y += b3.y;

        // combine quarter-warps: lanes 0-7 end with the full sums
        #pragma unroll
        for (int ofs = 16; ofs >= 8; ofs >>= 1) {
            a0.x += __shfl_down_sync(0xffffffff, a0.x, ofs);
            a0.y += __shfl_down_sync(0xffffffff, a0.y, ofs);
            a1.x += __shfl_down_sync(0xffffffff, a1.x, ofs);
            a1.y += __shfl_down_sync(0xffffffff, a1.y, ofs);
            a2.x += __shfl_down_sync(0xffffffff, a2.x, ofs);
            a2.y += __shfl_down_sync(0xffffffff, a2.y, ofs);
            a3.x += __shfl_down_sync(0xffffffff, a3.x, ofs);
            a3.y += __shfl_down_sync(0xffffffff, a3.y, ofs);
        }
        if (q == 0) {
            float2* sp2 = (float2*)sP[w];
            a0.x *= inv_t; a0.y *= inv_t;
            a1.x *= inv_t; a1.y *= inv_t;
            a2.x *= inv_t; a2.y *= inv_t;
            a3.x *= inv_t; a3.y *= inv_t;
            sp2[fl * 4 + 0] = a0;
            sp2[fl * 4 + 1] = a1;
            sp2[fl * 4 + 2] = a2;
            sp2[fl * 4 + 3] = a3;
        }
        __syncwarp();

        // GEMV: lane computes output units lane and lane+32
        float o0 = sB[lane];
        float o1 = sB[lane + 32];
        #pragma unroll
        for (int k = 0; k < D_FEAT; k++) {
            float pk = sP[w][k];
            o0 = fmaf(pk, sW[k * UNITS + lane],      o0);
            o1 = fmaf(pk, sW[k * UNITS + lane + 32], o1);
        }
        out[n * UNITS + lane]      = fmaxf(o0, 0.f);
        out[n * UNITS + lane + 32] = fmaxf(o1, 0.f);
        __syncwarp();
    }
}

// ---------------------------------------------------------------------------
extern "C" void kernel_launch(void* const* d_in, const int* in_sizes, int n_in,
                              void* d_out, int out_size) {
    const float* x      = (const float*)d_in[0];
    const float* W      = (const float*)d_in[1];
    const float* b      = (const float*)d_in[2];
    const int*   source = (const int*)d_in[3];
    const int*   target = (const int*)d_in[4];
    float* out = (float*)d_out;

    const int T = 256;
    k_zero_deg<<<(N_NODES + T - 1) / T, T>>>();
    k_degree<<<(N_EDGES + T - 1) / T, T>>>(target);
    k_scan1<<<N_SCANB, SCAN_B>>>();
    k_scan3_norm<<<N_SCANB, SCAN_B>>>((const float2*)x);
    k_place<<<(N_EDGES + T - 1) / T, T>>>(source, target);
    int fuse_blocks = (N_NODES + NODES_PER_BLK - 1) / NODES_PER_BLK;
    k_fused<<<fuse_blocks, FUSE_THREADS>>>(W, b, out);
}

// round 10
// speedup vs baseline: 1.2323x; 1.2323x over previous
#include <cuda_runtime.h>
#include <cuda_fp16.h>
#include <cuda_bf16.h>
#include <mma.h>

using namespace nvcuda;

#define N_NODES 100000
#define N_EDGES 1600000
#define D_FEAT  64
#define UNITS   64
#define SCAN_B  1024
#define N_SCANB ((N_NODES + SCAN_B - 1) / SCAN_B)   // 98

// ---- scratch (__device__ globals; no allocations allowed) -----------------
__device__ int    g_deg[N_NODES];
__device__ int    g_excl[N_NODES];
__device__ int    g_off[N_NODES + 1];
__device__ int    g_bsum[128];
__device__ float  g_inv[N_NODES];
__device__ int    g_pos[N_EDGES];            // edge's rank within its target
__device__ int    g_sorted_src[N_EDGES];
__device__ uint4  g_y4[N_NODES * 8];         // fp16 Y = (inv*x)@W : 128 B/node

// ---------------------------------------------------------------------------
__global__ void k_zero_deg() {
    int i = blockIdx.x * blockDim.x + threadIdx.x;
    if (i < N_NODES) g_deg[i] = 0;
}

// degree + per-edge rank in one atomic pass
__global__ void k_degree(const int* __restrict__ target) {
    int e = blockIdx.x * blockDim.x + threadIdx.x;
    if (e < N_EDGES) g_pos[e] = atomicAdd(&g_deg[target[e]], 1);
}

// ---- block-local exclusive scan of degrees --------------------------------
__global__ __launch_bounds__(SCAN_B) void k_scan1() {
    __shared__ int sh[SCAN_B];
    int tid = threadIdx.x;
    int i = blockIdx.x * SCAN_B + tid;
    int v = (i < N_NODES) ? g_deg[i] : 0;
    sh[tid] = v;
    __syncthreads();
    #pragma unroll
    for (int ofs = 1; ofs < SCAN_B; ofs <<= 1) {
        int t = (tid >= ofs) ? sh[tid - ofs] : 0;
        __syncthreads();
        sh[tid] += t;
        __syncthreads();
    }
    if (i < N_NODES) g_excl[i] = sh[tid] - v;
    if (tid == SCAN_B - 1) g_bsum[blockIdx.x] = sh[tid];
}

// ---- finish scan (per-block prefix of g_bsum) + inv -----------------------
__global__ __launch_bounds__(SCAN_B) void k_scan3() {
    __shared__ int s_add;
    int tid = threadIdx.x;
    int blk = blockIdx.x;

    if (tid < 32) {
        int acc = 0;
        for (int k = tid; k < blk; k += 32) acc += g_bsum[k];
        #pragma unroll
        for (int ofs = 16; ofs > 0; ofs >>= 1)
            acc += __shfl_down_sync(0xffffffff, acc, ofs);
        if (tid == 0) s_add = acc;
    }
    __syncthreads();
    int add = s_add;

    int i = blk * SCAN_B + tid;
    if (i < N_NODES) {
        g_off[i] = g_excl[i] + add;
        g_inv[i] = rsqrtf((float)g_deg[i]);
    }
    if (i == 0) g_off[N_NODES] = N_EDGES;
}

// ---- place edges into CSR (no atomics) ------------------------------------
__global__ void k_place(const int* __restrict__ source,
                        const int* __restrict__ target) {
    int e = blockIdx.x * blockDim.x + threadIdx.x;
    if (e >= N_EDGES) return;
    g_sorted_src[g_off[target[e]] + g_pos[e]] = source[e];
}

// ---------------------------------------------------------------------------
// Dense GEMM: Y[n,:] = fp16( inv[n] * (x[n,:] @ W) )  via tf32 wmma.
// Block = 256 threads = 8 warps; each warp a 16x64 row stripe.
// ---------------------------------------------------------------------------
#define GEMM_THREADS  256
#define GEMM_WARPS    8
#define ROWS_PER_BLK  (GEMM_WARPS * 16)    // 128
#define N_ROWTILES    (N_NODES / 16)       // 6250 (exact)
#define GEMM_BLOCKS   ((N_ROWTILES + GEMM_WARPS - 1) / GEMM_WARPS)   // 782

__global__ __launch_bounds__(GEMM_THREADS) void k_gemm(
    const float* __restrict__ x,
    const float* __restrict__ W)
{
    __shared__ float sW[D_FEAT * UNITS];          // 16 KB
    __shared__ float sC[ROWS_PER_BLK * UNITS];    // 32 KB

    int tid = threadIdx.x;
    #pragma unroll
    for (int i = 0; i < (D_FEAT * UNITS) / GEMM_THREADS; i++)
        sW[tid + i * GEMM_THREADS] = W[tid + i * GEMM_THREADS];
    __syncthreads();

    int w = tid >> 5;
    int tile_row = blockIdx.x * GEMM_WARPS + w;
    if (tile_row < N_ROWTILES) {
        wmma::fragment<wmma::accumulator, 16, 16, 8, float> c[4];
        #pragma unroll
        for (int n = 0; n < 4; n++) wmma::fill_fragment(c[n], 0.f);

        const float* abase = x + tile_row * 16 * D_FEAT;
        #pragma unroll
        for (int k = 0; k < 8; k++) {
            wmma::fragment<wmma::matrix_a, 16, 16, 8,
                           wmma::precision::tf32, wmma::row_major> a;
            wmma::load_matrix_sync(a, abase + k * 8, D_FEAT);
            #pragma unroll
            for (int i = 0; i < a.num_elements; i++)
                a.x[i] = wmma::__float_to_tf32(a.x[i]);
            #pragma unroll
            for (int n = 0; n < 4; n++) {
                wmma::fragment<wmma::matrix_b, 16, 16, 8,
                               wmma::precision::tf32, wmma::row_major> bf;
                wmma::load_matrix_sync(bf, sW + (k * 8) * UNITS + n * 16, UNITS);
                #pragma unroll
                for (int i = 0; i < bf.num_elements; i++)
                    bf.x[i] = wmma::__float_to_tf32(bf.x[i]);
                wmma::mma_sync(c[n], a, bf, c[n]);
            }
        }
        #pragma unroll
        for (int n = 0; n < 4; n++)
            wmma::store_matrix_sync(sC + (w * 16) * UNITS + n * 16, c[n],
                                    UNITS, wmma::mem_row_major);
    }
    __syncthreads();

    // epilogue: scale rows by inv, convert to fp16, store
    int base_row = blockIdx.x * ROWS_PER_BLK;
    __half2* y2 = (__half2*)g_y4;
    #pragma unroll
    for (int i = 0; i < (ROWS_PER_BLK * UNITS / 2) / GEMM_THREADS; i++) {
        int idx = tid + i * GEMM_THREADS;    // half2 slot in block tile
        int lr  = idx >> 5;                  // local row (32 half2 per row)
        int c2  = idx & 31;
        int row = base_row + lr;
        if (row < N_NODES) {
            float s = g_inv[row];
            float2 v;
            v.x = sC[lr * UNITS + c2 * 2]     * s;
            v.y = sC[lr * UNITS + c2 * 2 + 1] * s;
            y2[row * 32 + c2] = __float22half2_rn(v);
        }
    }
}

// ---------------------------------------------------------------------------
// Gather: out[n] = relu( inv[n] * sum_{s in row(n)} Y[s] + b )
// Warp per node pair; 4 quarter-warps interleave edges; one LDG.128 per
// octet per edge (Y row = 128 B). No GEMV, no weight smem.
// ---------------------------------------------------------------------------
#define NODES_PER_WARP 2
#define GATH_THREADS   512
#define NODES_PER_GBLK ((GATH_THREADS / 32) * NODES_PER_WARP)   // 32

__global__ __launch_bounds__(GATH_THREADS) void k_gather(
    const float* __restrict__ b,
    float* __restrict__ out)
{
    __shared__ float sB[UNITS];
    int tid  = threadIdx.x;
    int lane = tid & 31;
    int w    = tid >> 5;
    int q    = lane >> 3;    // quarter-warp: which edge of a group of 4
    int fl   = lane & 7;     // uint4 slot within the 128-B row

    if (tid < UNITS) sB[tid] = b[tid];
    __syncthreads();

    #pragma unroll
    for (int r = 0; r < NODES_PER_WARP; r++) {
        int n = blockIdx.x * NODES_PER_GBLK + w * NODES_PER_WARP + r;
        if (n >= N_NODES) return;

        int beg = g_off[n];
        int end = g_off[n + 1];
        float inv_t = g_inv[n];

        float2 a0 = make_float2(0.f, 0.f), a1 = a0, a2 = a0, a3 = a0;
        float2 b0 = a0, b1 = a0, b2 = a0, b3 = a0;

        int e = beg + q;
        for (; e + 4 < end; e += 8) {
            int s0 = g_sorted_src[e];
            int s1 = g_sorted_src[e + 4];
            uint4 u0 = g_y4[s0 * 8 + fl];
            uint4 u1 = g_y4[s1 * 8 + fl];
            const __half2* h0 = (const __half2*)&u0;
            const __half2* h1 = (const __half2*)&u1;
            float2 f;
            f = __half22float2(h0[0]); a0.x += f.x; a0.y += f.y;
            f = __half22float2(h0[1]); a1.x += f.x; a1.y += f.y;
            f = __half22float2(h0[2]); a2.x += f.x; a2.y += f.y;
            f = __half22float2(h0[3]); a3.x += f.x; a3.y += f.y;
            f = __half22float2(h1[0]); b0.x += f.x; b0.y += f.y;
            f = __half22float2(h1[1]); b1.x += f.x; b1.y += f.y;
            f = __half22float2(h1[2]); b2.x += f.x; b2.y += f.y;
            f = __half22float2(h1[3]); b3.x += f.x; b3.y += f.y;
        }
        if (e < end) {
            int s0 = g_sorted_src[e];
            uint4 u0 = g_y4[s0 * 8 + fl];
            const __half2* h0 = (const __half2*)&u0;
            float2 f;
            f = __half22float2(h0[0]); a0.x += f.x; a0.y += f.y;
            f = __half22float2(h0[1]); a1.x += f.x; a1.y += f.y;
            f = __half22float2(h0[2]); a2.x += f.x; a2.y += f.y;
            f = __half22float2(h0[3]); a3.x += f.x; a3.y += f.y;
        }

        a0.x += b0.x; a0.y += b0.y;  a1.x += b1.x; a1.y += b1.y;
        a2.x += b2.x; a2.y += b2.y;  a3.x += b3.x; a3.y += b3.y;

        // combine quarter-warps: lanes 0-7 end with full sums for cols fl*8..+7
        #pragma unroll
        for (int ofs = 16; ofs >= 8; ofs >>= 1) {
            a0.x += __shfl_down_sync(0xffffffff, a0.x, ofs);
            a0.y += __shfl_down_sync(0xffffffff, a0.y, ofs);
            a1.x += __shfl_down_sync(0xffffffff, a1.x, ofs);
            a1.y += __shfl_down_sync(0xffffffff, a1.y, ofs);
            a2.x += __shfl_down_sync(0xffffffff, a2.x, ofs);
            a2.y += __shfl_down_sync(0xffffffff, a2.y, ofs);
            a3.x += __shfl_down_sync(0xffffffff, a3.x, ofs);
            a3.y += __shfl_down_sync(0xffffffff, a3.y, ofs);
        }
        if (q == 0) {
            int cb = fl * 8;
            float4 o0, o1;
            o0.x = fmaxf(fmaf(inv_t, a0.x, sB[cb + 0]), 0.f);
            o0.y = fmaxf(fmaf(inv_t, a0.y, sB[cb + 1]), 0.f);
            o0.z = fmaxf(fmaf(inv_t, a1.x, sB[cb + 2]), 0.f);
            o0.w = fmaxf(fmaf(inv_t, a1.y, sB[cb + 3]), 0.f);
            o1.x = fmaxf(fmaf(inv_t, a2.x, sB[cb + 4]), 0.f);
            o1.y = fmaxf(fmaf(inv_t, a2.y, sB[cb + 5]), 0.f);
            o1.z = fmaxf(fmaf(inv_t, a3.x, sB[cb + 6]), 0.f);
            o1.w = fmaxf(fmaf(inv_t, a3.y, sB[cb + 7]), 0.f);
            float4* out4 = (float4*)(out + n * UNITS);
            out4[fl * 2]     = o0;
            out4[fl * 2 + 1] = o1;
        }
        __syncwarp();
    }
}

// ---------------------------------------------------------------------------
extern "C" void kernel_launch(void* const* d_in, const int* in_sizes, int n_in,
                              void* d_out, int out_size) {
    const float* x      = (const float*)d_in[0];
    const float* W      = (const float*)d_in[1];
    const float* b      = (const float*)d_in[2];
    const int*   source = (const int*)d_in[3];
    const int*   target = (const int*)d_in[4];
    float* out = (float*)d_out;

    const int T = 256;
    k_zero_deg<<<(N_NODES + T - 1) / T, T>>>();
    k_degree<<<(N_EDGES + T - 1) / T, T>>>(target);
    k_scan1<<<N_SCANB, SCAN_B>>>();
    k_scan3<<<N_SCANB, SCAN_B>>>();
    k_place<<<(N_EDGES + T - 1) / T, T>>>(source, target);
    k_gemm<<<GEMM_BLOCKS, GEMM_THREADS>>>(x, W);
    k_gather<<<(N_NODES + NODES_PER_GBLK - 1) / NODES_PER_GBLK, GATH_THREADS>>>(b, out);
}